// round 6
// baseline (speedup 1.0000x reference)
#include <cuda_runtime.h>

// MultiScaleDeformableAttention (bs=8, nq=900, nh=8, d=32, nl=4, npt=4)
// value: (8,22223,8,32) f32 | loc: (8,900,8,4,4,2) f32 | aw: (8,900,8,4,4) f32
// out: (8,900,256) f32
//
// 4 units per warp (group=lane>>3, chan=(lane&7)*4), LDG.128 gathers.
// R5: same pairing/smem staging as R4, but __launch_bounds__(256,5)
// (51-reg budget -> 40 warps/SM) to recover occupancy while keeping MLP=8.

#define MSDA_NQ   900
#define MSDA_NH   8
#define MSDA_D    32
#define MSDA_KEYS 22223
#define KEY_STRIDE 256
#define MSDA_UNITS (8 * MSDA_NQ * MSDA_NH)   // 57600
#define UNITS_PER_BLOCK 32

typedef unsigned long long u64t;

__device__ __forceinline__ u64t pk2(float a) {
    u64t r; asm("mov.b64 %0, {%1, %1};" : "=l"(r) : "f"(a)); return r;
}
__device__ __forceinline__ void fma2(u64t& d, u64t a, u64t b) {
    asm("fma.rn.f32x2 %0, %1, %2, %0;" : "+l"(d) : "l"(a), "l"(b));
}
__device__ __forceinline__ void add2(u64t& d, u64t a) {
    asm("add.rn.f32x2 %0, %0, %1;" : "+l"(d) : "l"(a));
}

template <int L> struct Level;
template <> struct Level<0> { static constexpr int H = 100, W = 167, START = 0;     };
template <> struct Level<1> { static constexpr int H = 50,  W = 84,  START = 16700; };
template <> struct Level<2> { static constexpr int H = 25,  W = 42,  START = 20900; };
template <> struct Level<3> { static constexpr int H = 13,  W = 21,  START = 21950; };

// Per-point address + corner-coefficient prep (pure ALU, inputs from smem).
// Offsets are BYTE offsets from the level base.
template <int Hd, int Wd>
__device__ __forceinline__ void prep(
    const float2 lxy, const float w,
    int& o00, int& o01, int& o10, int& o11,
    float& c00, float& c01, float& c10, float& c11)
{
    const float x = fmaf(lxy.x, (float)Wd, -0.5f);
    const float y = fmaf(lxy.y, (float)Hd, -0.5f);
    const int x0 = __float2int_rd(x);
    const int y0 = __float2int_rd(y);
    const float wx1 = x - (float)x0, wy1 = y - (float)y0;
    const float wx0 = 1.0f - wx1,    wy0 = 1.0f - wy1;

    const bool vx0 = (unsigned)x0       < (unsigned)Wd;
    const bool vx1 = (unsigned)(x0 + 1) < (unsigned)Wd;
    const bool vy0 = (unsigned)y0       < (unsigned)Hd;
    const bool vy1 = (unsigned)(y0 + 1) < (unsigned)Hd;

    const int x0c = min(max(x0, 0), Wd - 1);
    const int x1c = min(max(x0 + 1, 0), Wd - 1);
    const int y0c = min(max(y0, 0), Hd - 1);
    const int y1c = min(max(y0 + 1, 0), Hd - 1);

    const int r0 = y0c * Wd, r1 = y1c * Wd;
    o00 = (r0 + x0c) << 10;  o01 = (r0 + x1c) << 10;   // key * 1024 bytes
    o10 = (r1 + x0c) << 10;  o11 = (r1 + x1c) << 10;

    const float wwy0 = w * wy0, wwy1 = w * wy1;
    c00 = (vx0 && vy0) ? wx0 * wwy0 : 0.0f;
    c01 = (vx1 && vy0) ? wx1 * wwy0 : 0.0f;
    c10 = (vx0 && vy1) ? wx0 * wwy1 : 0.0f;
    c11 = (vx1 && vy1) ? wx1 * wwy1 : 0.0f;
}

__device__ __forceinline__ ulonglong2 ldg128(const char* base, int byte_off) {
    return __ldg((const ulonglong2*)(base + byte_off));
}

template <int L>
__device__ __forceinline__ void sample_level(
    const char* __restrict__ vlane,    // byte pointer: value + b-off + h*32 + c4
    const float2* __restrict__ locs,   // smem, this unit's 16 points
    const float*  __restrict__ aws,    // smem, this unit's 16 weights
    u64t& a0, u64t& a1, u64t& b0, u64t& b1)
{
    const char* __restrict__ vlev =
        vlane + (size_t)Level<L>::START * (KEY_STRIDE * 4);

    #pragma unroll
    for (int pp = 0; pp < 2; pp++) {
        const int iA = L * 4 + pp * 2;
        const int iB = iA + 1;

        // prep A, issue A loads (prep-A temps die before B prep)
        int aO00, aO01, aO10, aO11;  float aC00, aC01, aC10, aC11;
        prep<Level<L>::H, Level<L>::W>(locs[iA], aws[iA],
                                       aO00, aO01, aO10, aO11,
                                       aC00, aC01, aC10, aC11);
        const ulonglong2 vA00 = ldg128(vlev, aO00);
        const ulonglong2 vA01 = ldg128(vlev, aO01);
        const ulonglong2 vA10 = ldg128(vlev, aO10);
        const ulonglong2 vA11 = ldg128(vlev, aO11);

        int bO00, bO01, bO10, bO11;  float bC00, bC01, bC10, bC11;
        prep<Level<L>::H, Level<L>::W>(locs[iB], aws[iB],
                                       bO00, bO01, bO10, bO11,
                                       bC00, bC01, bC10, bC11);
        const ulonglong2 vB00 = ldg128(vlev, bO00);
        const ulonglong2 vB01 = ldg128(vlev, bO01);
        const ulonglong2 vB10 = ldg128(vlev, bO10);
        const ulonglong2 vB11 = ldg128(vlev, bO11);

        // consume A first (frees its 16 data regs), then B
        const u64t pA00 = pk2(aC00), pA01 = pk2(aC01);
        const u64t pA10 = pk2(aC10), pA11 = pk2(aC11);
        fma2(a0, pA00, vA00.x);  fma2(a1, pA00, vA00.y);
        fma2(a0, pA01, vA01.x);  fma2(a1, pA01, vA01.y);
        fma2(a0, pA10, vA10.x);  fma2(a1, pA10, vA10.y);
        fma2(a0, pA11, vA11.x);  fma2(a1, pA11, vA11.y);

        const u64t pB00 = pk2(bC00), pB01 = pk2(bC01);
        const u64t pB10 = pk2(bC10), pB11 = pk2(bC11);
        fma2(b0, pB00, vB00.x);  fma2(b1, pB00, vB00.y);
        fma2(b0, pB01, vB01.x);  fma2(b1, pB01, vB01.y);
        fma2(b0, pB10, vB10.x);  fma2(b1, pB10, vB10.y);
        fma2(b0, pB11, vB11.x);  fma2(b1, pB11, vB11.y);
    }
}

__global__ __launch_bounds__(256, 5) void msda_kernel(
    const float*  __restrict__ value,
    const float2* __restrict__ loc,
    const float*  __restrict__ aw,
    float* __restrict__ out)
{
    __shared__ float2 loc_s[UNITS_PER_BLOCK][17];  // pad: groups hit distinct banks
    __shared__ float  aw_s [UNITS_PER_BLOCK][17];

    const int tid = threadIdx.x;
    const int u0  = blockIdx.x * UNITS_PER_BLOCK;

    // Cooperative staging: loc = 32 units * 16 float2 = 256 float4 (1/thread),
    // aw = 32 units * 16 f32 = 128 float4 (first 128 threads).
    {
        const float4 v = __ldg((const float4*)(loc + (size_t)u0 * 16) + tid);
        const int unit = (2 * tid) >> 4;
        const int pos  = (2 * tid) & 15;
        loc_s[unit][pos]     = make_float2(v.x, v.y);
        loc_s[unit][pos + 1] = make_float2(v.z, v.w);
        if (tid < 128) {
            const float4 a = __ldg((const float4*)(aw + (size_t)u0 * 16) + tid);
            const int au = (4 * tid) >> 4;
            const int ap = (4 * tid) & 15;
            aw_s[au][ap]     = a.x;  aw_s[au][ap + 1] = a.y;
            aw_s[au][ap + 2] = a.z;  aw_s[au][ap + 3] = a.w;
        }
    }
    __syncthreads();

    const int lu = tid >> 3;             // local unit 0..31
    const int u  = u0 + lu;              // global (b,q,h) unit
    const int c4 = (tid & 7) << 2;       // channel base

    const int h = u & 7;
    const int b = u / (MSDA_NQ * MSDA_NH);

    const char* __restrict__ vlane = (const char*)
        (value + (size_t)b * (MSDA_KEYS * KEY_STRIDE) + h * MSDA_D + c4);

    u64t a0 = 0, a1 = 0, b0 = 0, b1 = 0;
    sample_level<0>(vlane, loc_s[lu], aw_s[lu], a0, a1, b0, b1);
    sample_level<1>(vlane, loc_s[lu], aw_s[lu], a0, a1, b0, b1);
    sample_level<2>(vlane, loc_s[lu], aw_s[lu], a0, a1, b0, b1);
    sample_level<3>(vlane, loc_s[lu], aw_s[lu], a0, a1, b0, b1);

    add2(a0, b0);
    add2(a1, b1);

    float f0, f1, f2, f3;
    asm("mov.b64 {%0, %1}, %2;" : "=f"(f0), "=f"(f1) : "l"(a0));
    asm("mov.b64 {%0, %1}, %2;" : "=f"(f2), "=f"(f3) : "l"(a1));
    *(float4*)(out + (size_t)u * MSDA_D + c4) = make_float4(f0, f1, f2, f3);
}

extern "C" void kernel_launch(void* const* d_in, const int* in_sizes, int n_in,
                              void* d_out, int out_size)
{
    const float*  value = (const float*)d_in[0];
    const float2* locp  = (const float2*)d_in[1];
    const float*  aw    = (const float*)d_in[2];
    float* out = (float*)d_out;

    const int blocks = MSDA_UNITS / UNITS_PER_BLOCK;   // 1800, exact
    msda_kernel<<<blocks, 256>>>(value, locp, aw, out);
}

// round 7
// speedup vs baseline: 1.0653x; 1.0653x over previous
#include <cuda_runtime.h>

// MultiScaleDeformableAttention (bs=8, nq=900, nh=8, d=32, nl=4, npt=4)
// value: (8,22223,8,32) f32 | loc: (8,900,8,4,4,2) f32 | aw: (8,900,8,4,4) f32
// out: (8,900,256) f32
//
// R6: two-phase. Phase 1 splits per-point prep across the 8 lanes of each
// unit (lane j preps points 2j,2j+1) and stores offsets+coeffs to smem.
// Phase 2 is a lean gather loop: LDS.128 broadcast + 4x LDG.128 + f32x2 FMA,
// points processed in pairs (8 gathers in flight).

#define MSDA_NQ   900
#define MSDA_NH   8
#define MSDA_D    32
#define MSDA_KEYS 22223
#define MSDA_UNITS (8 * MSDA_NQ * MSDA_NH)   // 57600
#define UNITS_PER_BLOCK 32

typedef unsigned long long u64t;

__device__ __forceinline__ u64t pk2(float a) {
    u64t r; asm("mov.b64 %0, {%1, %1};" : "=l"(r) : "f"(a)); return r;
}
__device__ __forceinline__ void fma2(u64t& d, u64t a, u64t b) {
    asm("fma.rn.f32x2 %0, %1, %2, %0;" : "+l"(d) : "l"(a), "l"(b));
}
__device__ __forceinline__ void add2(u64t& d, u64t a) {
    asm("add.rn.f32x2 %0, %0, %1;" : "+l"(d) : "l"(a));
}
__device__ __forceinline__ ulonglong2 ldg128(const char* base, int byte_off) {
    return __ldg((const ulonglong2*)(base + byte_off));
}

// Prep one point: absolute byte offsets (incl. level start) + corner coeffs.
__device__ __forceinline__ void prep_point(
    float lx, float ly, float w, int Wd, int Hd, int start_bytes,
    int4* __restrict__ op, float4* __restrict__ cp)
{
    const float x = fmaf(lx, (float)Wd, -0.5f);
    const float y = fmaf(ly, (float)Hd, -0.5f);
    const int x0 = __float2int_rd(x);
    const int y0 = __float2int_rd(y);
    const float wx1 = x - (float)x0, wy1 = y - (float)y0;
    const float wx0 = 1.0f - wx1,    wy0 = 1.0f - wy1;

    const bool vx0 = (unsigned)x0       < (unsigned)Wd;
    const bool vx1 = (unsigned)(x0 + 1) < (unsigned)Wd;
    const bool vy0 = (unsigned)y0       < (unsigned)Hd;
    const bool vy1 = (unsigned)(y0 + 1) < (unsigned)Hd;

    const int x0c = min(max(x0, 0), Wd - 1);
    const int x1c = min(max(x0 + 1, 0), Wd - 1);
    const int y0c = min(max(y0, 0), Hd - 1);
    const int y1c = min(max(y0 + 1, 0), Hd - 1);

    const int r0 = y0c * Wd, r1 = y1c * Wd;
    // key stride = 256 floats = 1024 bytes
    *op = make_int4(start_bytes + ((r0 + x0c) << 10),
                    start_bytes + ((r0 + x1c) << 10),
                    start_bytes + ((r1 + x0c) << 10),
                    start_bytes + ((r1 + x1c) << 10));

    const float wwy0 = w * wy0, wwy1 = w * wy1;
    *cp = make_float4(vx0 && vy0 ? wx0 * wwy0 : 0.0f,
                      vx1 && vy0 ? wx1 * wwy0 : 0.0f,
                      vx0 && vy1 ? wx0 * wwy1 : 0.0f,
                      vx1 && vy1 ? wx1 * wwy1 : 0.0f);
}

__global__ __launch_bounds__(256, 4) void msda_kernel(
    const float* __restrict__ value,
    const float* __restrict__ loc,
    const float* __restrict__ aw,
    float* __restrict__ out)
{
    // point-major: iter p reads [p][lu]; 4 groups/warp -> 4 consecutive 16B
    // chunks (conflict-free). +1 pad de-conflicts phase-1 writes.
    __shared__ int4   off_s[16][UNITS_PER_BLOCK + 1];
    __shared__ float4 cf_s [16][UNITS_PER_BLOCK + 1];

    const int tid = threadIdx.x;
    const int u0  = blockIdx.x * UNITS_PER_BLOCK;
    const int lu  = tid >> 3;       // local unit 0..31
    const int j   = tid & 7;        // lane within unit

    // ---- Phase 1: lane j preps points 2j, 2j+1 of its unit ----
    {
        // loc: 8 float4 per unit; aw: 8 float2 per unit. Index u0*8+tid is
        // exactly (unit = tid>>3, pair = tid&7): fully coalesced.
        const float4 l2 = __ldg((const float4*)loc + (size_t)u0 * 8 + tid);
        const float2 w2 = __ldg((const float2*)aw  + (size_t)u0 * 8 + tid);

        const int lvl = j >> 1;     // points 2j,2j+1 share level p>>2
        const int Wd = lvl == 0 ? 167 : lvl == 1 ? 84 : lvl == 2 ? 42 : 21;
        const int Hd = lvl == 0 ? 100 : lvl == 1 ? 50 : lvl == 2 ? 25 : 13;
        const int sb = lvl == 0 ? 0
                     : lvl == 1 ? 16700 * 1024
                     : lvl == 2 ? 20900 * 1024
                     :            21950 * 1024;

        prep_point(l2.x, l2.y, w2.x, Wd, Hd, sb, &off_s[2*j][lu],   &cf_s[2*j][lu]);
        prep_point(l2.z, l2.w, w2.y, Wd, Hd, sb, &off_s[2*j+1][lu], &cf_s[2*j+1][lu]);
    }
    __syncthreads();

    // ---- Phase 2: lean gather loop ----
    const int u  = u0 + lu;
    const int c4 = j << 2;          // channel base 0..28
    const int h  = u & 7;
    const int b  = u / (MSDA_NQ * MSDA_NH);

    const char* __restrict__ vbase = (const char*)
        (value + (size_t)b * (MSDA_KEYS * 256) + h * MSDA_D + c4);

    u64t a0 = 0, a1 = 0, b0 = 0, b1 = 0;

    #pragma unroll
    for (int p = 0; p < 16; p += 2) {
        const int4   oA = off_s[p][lu];
        const float4 cA = cf_s [p][lu];
        const int4   oB = off_s[p + 1][lu];
        const float4 cB = cf_s [p + 1][lu];

        // 8 independent 128-bit gathers in flight
        const ulonglong2 vA00 = ldg128(vbase, oA.x);
        const ulonglong2 vA01 = ldg128(vbase, oA.y);
        const ulonglong2 vA10 = ldg128(vbase, oA.z);
        const ulonglong2 vA11 = ldg128(vbase, oA.w);
        const ulonglong2 vB00 = ldg128(vbase, oB.x);
        const ulonglong2 vB01 = ldg128(vbase, oB.y);
        const ulonglong2 vB10 = ldg128(vbase, oB.z);
        const ulonglong2 vB11 = ldg128(vbase, oB.w);

        const u64t pA00 = pk2(cA.x), pA01 = pk2(cA.y);
        const u64t pA10 = pk2(cA.z), pA11 = pk2(cA.w);
        fma2(a0, pA00, vA00.x);  fma2(a1, pA00, vA00.y);
        fma2(a0, pA01, vA01.x);  fma2(a1, pA01, vA01.y);
        fma2(a0, pA10, vA10.x);  fma2(a1, pA10, vA10.y);
        fma2(a0, pA11, vA11.x);  fma2(a1, pA11, vA11.y);

        const u64t pB00 = pk2(cB.x), pB01 = pk2(cB.y);
        const u64t pB10 = pk2(cB.z), pB11 = pk2(cB.w);
        fma2(b0, pB00, vB00.x);  fma2(b1, pB00, vB00.y);
        fma2(b0, pB01, vB01.x);  fma2(b1, pB01, vB01.y);
        fma2(b0, pB10, vB10.x);  fma2(b1, pB10, vB10.y);
        fma2(b0, pB11, vB11.x);  fma2(b1, pB11, vB11.y);
    }

    add2(a0, b0);
    add2(a1, b1);

    float f0, f1, f2, f3;
    asm("mov.b64 {%0, %1}, %2;" : "=f"(f0), "=f"(f1) : "l"(a0));
    asm("mov.b64 {%0, %1}, %2;" : "=f"(f2), "=f"(f3) : "l"(a1));
    *(float4*)(out + (size_t)u * MSDA_D + c4) = make_float4(f0, f1, f2, f3);
}

extern "C" void kernel_launch(void* const* d_in, const int* in_sizes, int n_in,
                              void* d_out, int out_size)
{
    const float* value = (const float*)d_in[0];
    const float* locp  = (const float*)d_in[1];
    const float* aw    = (const float*)d_in[2];
    float* out = (float*)d_out;

    const int blocks = MSDA_UNITS / UNITS_PER_BLOCK;   // 1800, exact
    msda_kernel<<<blocks, 256>>>(value, locp, aw, out);
}